// round 7
// baseline (speedup 1.0000x reference)
#include <cuda_runtime.h>
#include <math.h>
#include <stdint.h>

// RandomizedOscillatorsNetwork: B=128, T=1024, I=64, H=512
// 16 clusters x 8 CTAs; cluster owns 8 batch rows; CTA owns 64 H-cols, weight slice
// (h2h||x2h) [576x64] resident in SMEM. Per-step:
//   pass1 GEMM over LOCAL k (own 64 hy cols + 64 x cols) overlaps the cluster barrier;
//   pass2 GEMM reads peer hy DIRECTLY from L2 (__ldcg on double-buffered g_hy).
// NT=256 (8 warps): warp = k-slice, lane = 2 cols, batch pairs packed fma.rn.f32x2.

#define DTc 0.042f
#define Bn 128
#define Tn 1024
#define In 64
#define Hn 512
#define NT 256

#define W_BYTES   (576*64*4)             // 147456
#define VF_OFF    W_BYTES                // [128][8] floats: rows 0..63 own hy, 64..127 x
#define VF_BYTES  (128*8*4)              // 4096
#define RF_OFF    (VF_OFF + VF_BYTES)
#define RF_BYTES  (8*8*64*4)             // 16384  [warp][b][col]
#define SMEM_BYTES (RF_OFF + RF_BYTES)   // 167936

typedef unsigned long long u64;

// double-buffered per-cluster hy exchange: [buf][cluster][h][b] floats (16KB/cluster, L2-hot)
__device__ float g_hy[2][16][Hn][8];

__device__ __forceinline__ u64 pack2(float lo, float hi) {
    u64 r; asm("mov.b64 %0, {%1, %2};" : "=l"(r) : "f"(lo), "f"(hi)); return r;
}
__device__ __forceinline__ void unpack2(u64 v, float& lo, float& hi) {
    asm("mov.b64 {%0, %1}, %2;" : "=f"(lo), "=f"(hi) : "l"(v));
}
__device__ __forceinline__ u64 ffma2(u64 a, u64 b, u64 c) {
    u64 d; asm("fma.rn.f32x2 %0, %1, %2, %3;" : "=l"(d) : "l"(a), "l"(b), "l"(c)); return d;
}

#define GEMM8(hA, hB, wv)                                              \
    {   u64 w0 = pack2((wv).x, (wv).x), w1 = pack2((wv).y, (wv).y);    \
        a00 = ffma2((hA).x, w0, a00); a01 = ffma2((hA).x, w1, a01);    \
        a10 = ffma2((hA).y, w0, a10); a11 = ffma2((hA).y, w1, a11);    \
        a20 = ffma2((hB).x, w0, a20); a21 = ffma2((hB).x, w1, a21);    \
        a30 = ffma2((hB).y, w0, a30); a31 = ffma2((hB).y, w1, a31); }

__global__ __launch_bounds__(NT, 1) __cluster_dims__(8, 1, 1)
void ron_kernel(const float* __restrict__ x, const float* __restrict__ x2h,
                const float* __restrict__ h2h, const float* __restrict__ bias,
                const float* __restrict__ gam, const float* __restrict__ eps,
                float* __restrict__ out, long long out_elems)
{
    extern __shared__ char smem[];
    float* W  = (float*)smem;                 // [576][64] k-major (global h order; 512..575 = x2h)
    float* vf = (float*)(smem + VF_OFF);      // [128][8]: rows 0..63 own hy (h=c0+r), 64..127 x
    float* rf = (float*)(smem + RF_OFF);      // [8][8][64] split-K partials

    const int tid  = threadIdx.x;
    const int cl   = blockIdx.x >> 3;
    const int rank = blockIdx.x & 7;
    const int c0   = rank * 64;
    const int b0   = cl * 8;

    // prologue: resident weight slice
    for (int idx = tid; idx < 576*64; idx += NT) {
        int k = idx >> 6, j = idx & 63;
        W[idx] = (k < Hn) ? h2h[(size_t)k*Hn + c0 + j] : x2h[(size_t)(k - Hn)*Hn + c0 + j];
    }

    // epilogue mapping: thread owns (b4, col) and (b4+4, col)
    const int col = tid & 63, b4 = tid >> 6;      // b4 in 0..3
    const int hg  = c0 + col;
    const float bia = bias[hg], ga = gam[hg], ep = eps[hg];
    float hy0 = 0.f, hz0 = 0.f, hy1 = 0.f, hz1 = 0.f;

    // GEMM mapping: warp w in 0..7, lane cg owns cols {2cg, 2cg+1}
    const int w  = tid >> 5, cg = tid & 31;
    const int vrow0 = w * 16;                                      // vf row base for pass1
    const int wrow0 = (w < 4) ? (c0 + w*16) : (512 + (w - 4)*16);  // W row base for pass1
    const float* Wr1 = W  + wrow0*64 + cg*2;
    const float* vr1 = vf + vrow0*8;
    float*       rw  = rf + w*512 + cg*2;
    const int m0 = w * 56;                                         // pass2 peer-k base

    // x pointers: x[b][t][i] ; this thread stages (b0+b4, col) and (b0+b4+4, col)
    const float* xp0 = x + ((size_t)(b0 + b4)     * Tn) * In + col;
    const float* xp1 = x + ((size_t)(b0 + b4 + 4) * Tn) * In + col;

    // pre-loop: zero own-hy rows of vf, stage x(0)
    {
        float* v4 = vf + col*8;
        v4[b4] = 0.f; v4[b4 + 4] = 0.f;
        float* vx = vf + (64 + col)*8;
        vx[b4]     = xp0[0];
        vx[b4 + 4] = xp1[0];
    }
    const size_t BTH = (size_t)Bn * Tn * Hn;
    const bool writeFinal = (out_elems >= (long long)(BTH + (size_t)Bn * Hn));

    __syncthreads();

    for (int t = 0; t < Tn; t++) {
        // prefetch x(t+1) early: DRAM latency hidden behind the whole step
        const int tn = (t + 1 < Tn) ? (t + 1) : t;
        const float xn0 = xp0[(size_t)tn * In];
        const float xn1 = xp1[(size_t)tn * In];

        u64 a00=0ull,a01=0ull,a10=0ull,a11=0ull,a20=0ull,a21=0ull,a30=0ull,a31=0ull;

        // ---- pass1: local k (own hy slice + x), overlaps cluster barrier round
        #pragma unroll 4
        for (int kk = 0; kk < 16; kk++) {
            float2 wv = *(const float2*)(Wr1 + kk*64);            // conflict-free LDS.64
            const ulonglong2* hv = (const ulonglong2*)(vr1 + kk*8);
            ulonglong2 hA = hv[0];                                 // broadcast
            ulonglong2 hB = hv[1];
            GEMM8(hA, hB, wv);
        }

        if (t > 0) {
            // ---- wait for peers' hy(t) (arrive was issued last step, mostly elapsed)
            asm volatile("barrier.cluster.wait.aligned;" ::: "memory");
            // ---- pass2: peer k, read hy directly from L2 (lane-uniform -> 1 sector/load)
            const float* gb = &g_hy[(t - 1) & 1][cl][0][0];
            #pragma unroll 4
            for (int kk = 0; kk < 56; kk++) {
                int m = m0 + kk;
                int h = m + ((m >= c0) ? 64 : 0);                  // skip own slice
                const ulonglong2* gp = (const ulonglong2*)(gb + h*8);
                ulonglong2 hA = __ldcg(gp);
                ulonglong2 hB = __ldcg(gp + 1);
                float2 wv = *(const float2*)(W + h*64 + cg*2);
                GEMM8(hA, hB, wv);
            }
        }

        // ---- stage split-K partials [w][b][col]
        {
            float l0,h0,l1,h1;
            unpack2(a00,l0,h0); unpack2(a01,l1,h1);
            *(float2*)(rw + 0*64) = make_float2(l0,l1);
            *(float2*)(rw + 1*64) = make_float2(h0,h1);
            unpack2(a10,l0,h0); unpack2(a11,l1,h1);
            *(float2*)(rw + 2*64) = make_float2(l0,l1);
            *(float2*)(rw + 3*64) = make_float2(h0,h1);
            unpack2(a20,l0,h0); unpack2(a21,l1,h1);
            *(float2*)(rw + 4*64) = make_float2(l0,l1);
            *(float2*)(rw + 5*64) = make_float2(h0,h1);
            unpack2(a30,l0,h0); unpack2(a31,l1,h1);
            *(float2*)(rw + 6*64) = make_float2(l0,l1);
            *(float2*)(rw + 7*64) = make_float2(h0,h1);
        }
        __syncthreads();   // partials visible; pass1 vf reads done -> vf may be overwritten below

        // ---- reduce + oscillator update (2 outputs per thread)
        {
            float s0 = 0.f, s1 = 0.f;
            const float* r0 = rf + b4*64 + col;
            const float* r1 = r0 + 4*64;
            #pragma unroll
            for (int q = 0; q < 8; q++) { s0 += r0[q*512]; s1 += r1[q*512]; }
            float th0 = tanhf(s0 + bia);
            float th1 = tanhf(s1 + bia);
            hz0 += DTc * (th0 - ga*hy0 - ep*hz0);  hy0 += DTc * hz0;
            hz1 += DTc * (th1 - ga*hy1 - ep*hz1);  hy1 += DTc * hz1;

            // publish to peers (release happens at arrive below)
            float* gw = &g_hy[t & 1][cl][hg][0];
            gw[b4]     = hy0;
            gw[b4 + 4] = hy1;
            // own slice + next x into vf for next pass1
            float* v4 = vf + col*8;
            v4[b4] = hy0; v4[b4 + 4] = hy1;
            float* vx = vf + (64 + col)*8;
            vx[b4] = xn0; vx[b4 + 4] = xn1;
            // outputs
            size_t o0 = ((size_t)(b0 + b4) * Tn + t) * Hn + hg;
            out[o0]                        = hy0;
            out[o0 + (size_t)4 * Tn * Hn]  = hy1;
            if (t == Tn - 1 && writeFinal) {
                out[BTH + (size_t)(b0 + b4)     * Hn + hg] = hy0;
                out[BTH + (size_t)(b0 + b4 + 4) * Hn + hg] = hy1;
            }
        }
        // release our g_hy writes to the cluster; wait happens mid-next-step
        asm volatile("barrier.cluster.arrive.aligned;" ::: "memory");
        __syncthreads();   // vf staged before next pass1; rf reads done before next store
    }
    asm volatile("barrier.cluster.wait.aligned;" ::: "memory");
}

extern "C" void kernel_launch(void* const* d_in, const int* in_sizes, int n_in,
                              void* d_out, int out_size) {
    const float* x    = (const float*)d_in[0];
    const float* x2h  = (const float*)d_in[1];
    const float* h2h  = (const float*)d_in[2];
    const float* bias = (const float*)d_in[3];
    const float* gam  = (const float*)d_in[4];
    const float* eps  = (const float*)d_in[5];
    float* out = (float*)d_out;
    (void)in_sizes; (void)n_in;

    cudaFuncSetAttribute(ron_kernel, cudaFuncAttributeMaxDynamicSharedMemorySize, SMEM_BYTES);
    ron_kernel<<<128, NT, SMEM_BYTES>>>(x, x2h, h2h, bias, gam, eps, out, (long long)out_size);
}

// round 12
// speedup vs baseline: 2.4992x; 2.4992x over previous
#include <cuda_runtime.h>
#include <math.h>
#include <stdint.h>

// RandomizedOscillatorsNetwork: B=128, T=1024, I=64, H=512
// 16 clusters x 8 CTAs; cluster owns 8 batch rows; CTA owns 64 H-cols, weight slice
// (h2h||x2h) [576x64] resident in SMEM.
// Exchange: producer-push DSMEM bulk copies (cp.async.bulk shared::cta -> shared::cluster)
// with mbarrier complete_tx at each consumer; double-buffered vbuf; NO barrier.cluster
// and NO L2 traffic in the step loop. NT=256: warp = k-slice, lane = 2 cols,
// batch pairs packed fma.rn.f32x2, split-K partials reduced through smem.

#define DTc 0.042f
#define Bn 128
#define Tn 1024
#define In 64
#define Hn 512
#define NT 256

#define W_BYTES   (576*64*4)              // 147456
#define VB_OFF    W_BYTES                 // vbuf[2][512][8] floats (16KB each)
#define VB_BYTES  (2*512*8*4)             // 32768
#define XB_OFF    (VB_OFF + VB_BYTES)     // xbuf[64][8] floats
#define XB_BYTES  (64*8*4)                // 2048
#define RF_OFF    (XB_OFF + XB_BYTES)     // partials [8 warps][8 b][64 col]
#define RF_BYTES  (8*8*64*4)              // 16384
#define MB_OFF    (RF_OFF + RF_BYTES)     // mbarrier (16B aligned)
#define SMEM_BYTES (MB_OFF + 64)          // 198720

#define SLICE_BYTES 2048                  // 64 rows x 8 batches x 4B
#define STEP_TX     (7*SLICE_BYTES)       // inbound bytes per step per CTA

typedef unsigned long long u64;

__device__ __forceinline__ u64 pack2(float lo, float hi) {
    u64 r; asm("mov.b64 %0, {%1, %2};" : "=l"(r) : "f"(lo), "f"(hi)); return r;
}
__device__ __forceinline__ void unpack2(u64 v, float& lo, float& hi) {
    asm("mov.b64 {%0, %1}, %2;" : "=f"(lo), "=f"(hi) : "l"(v));
}
__device__ __forceinline__ u64 ffma2(u64 a, u64 b, u64 c) {
    u64 d; asm("fma.rn.f32x2 %0, %1, %2, %3;" : "=l"(d) : "l"(a), "l"(b), "l"(c)); return d;
}
__device__ __forceinline__ uint32_t smem_u32(const void* p) {
    uint32_t a; asm("{ .reg .u64 t; cvta.to.shared.u64 t, %1; cvt.u32.u64 %0, t; }"
                    : "=r"(a) : "l"(p)); return a;
}
__device__ __forceinline__ uint32_t mapa_u32(uint32_t addr, int rank) {
    uint32_t r; asm("mapa.shared::cluster.u32 %0, %1, %2;" : "=r"(r) : "r"(addr), "r"(rank));
    return r;
}
__device__ __forceinline__ void mbar_init(uint32_t mbar, uint32_t cnt) {
    asm volatile("mbarrier.init.shared.b64 [%0], %1;" :: "r"(mbar), "r"(cnt) : "memory");
}
__device__ __forceinline__ void mbar_expect(uint32_t mbar, uint32_t tx) {
    asm volatile("mbarrier.arrive.expect_tx.shared.b64 _, [%0], %1;" :: "r"(mbar), "r"(tx) : "memory");
}
__device__ __forceinline__ void mbar_wait(uint32_t mbar, uint32_t parity) {
    asm volatile(
        "{\n\t.reg .pred P1;\n"
        "W_%=:\n\t"
        "mbarrier.try_wait.parity.acquire.cta.shared::cta.b64 P1, [%0], %1, 0x989680;\n\t"
        "@P1 bra.uni D_%=;\n\t"
        "bra.uni W_%=;\n"
        "D_%=:\n\t}"
        :: "r"(mbar), "r"(parity) : "memory");
}
__device__ __forceinline__ void dsmem_push(uint32_t dst, uint32_t src, uint32_t bytes, uint32_t rmbar) {
    asm volatile(
        "cp.async.bulk.shared::cluster.shared::cta.mbarrier::complete_tx::bytes [%0], [%1], %2, [%3];"
        :: "r"(dst), "r"(src), "r"(bytes), "r"(rmbar) : "memory");
}

#define GEMM8(hA, hB, wv)                                              \
    {   u64 w0 = pack2((wv).x, (wv).x), w1 = pack2((wv).y, (wv).y);    \
        a00 = ffma2((hA).x, w0, a00); a01 = ffma2((hA).x, w1, a01);    \
        a10 = ffma2((hA).y, w0, a10); a11 = ffma2((hA).y, w1, a11);    \
        a20 = ffma2((hB).x, w0, a20); a21 = ffma2((hB).x, w1, a21);    \
        a30 = ffma2((hB).y, w0, a30); a31 = ffma2((hB).y, w1, a31); }

__global__ __launch_bounds__(NT, 1) __cluster_dims__(8, 1, 1)
void ron_kernel(const float* __restrict__ x, const float* __restrict__ x2h,
                const float* __restrict__ h2h, const float* __restrict__ bias,
                const float* __restrict__ gam, const float* __restrict__ eps,
                float* __restrict__ out, long long out_elems)
{
    extern __shared__ char smem[];
    float* W  = (float*)smem;                 // [576][64] global-k order (512..575 = x2h)
    float* vb = (float*)(smem + VB_OFF);      // [2][512][8] hy by global h index
    float* xb = (float*)(smem + XB_OFF);      // [64][8]
    float* rf = (float*)(smem + RF_OFF);      // [8][8][64]
    const uint32_t sbase = smem_u32(smem);
    const uint32_t mbar  = sbase + MB_OFF;

    const int tid  = threadIdx.x;
    const int cl   = blockIdx.x >> 3;
    const int rank = blockIdx.x & 7;
    const int c0   = rank * 64;
    const int b0   = cl * 8;

    // prologue: resident weight slice
    for (int idx = tid; idx < 576*64; idx += NT) {
        int k = idx >> 6, j = idx & 63;
        W[idx] = (k < Hn) ? h2h[(size_t)k*Hn + c0 + j] : x2h[(size_t)(k - Hn)*Hn + c0 + j];
    }

    // epilogue mapping: thread owns (b4, col) and (b4+4, col)
    const int col = tid & 63, b4 = tid >> 6;
    const int hg  = c0 + col;
    const float bia = bias[hg], ga = gam[hg], ep = eps[hg];
    float hy0 = 0.f, hz0 = 0.f, hy1 = 0.f, hz1 = 0.f;

    // GEMM mapping: warp w 0..7, lane cg owns cols {2cg, 2cg+1}
    const int w  = tid >> 5, cg = tid & 31;
    const int wrow0 = (w < 4) ? (c0 + w*16) : (512 + (w - 4)*16);   // pass1 W rows
    const float* Wr1 = W + wrow0*64 + cg*2;
    float*       rw  = rf + w*512 + cg*2;
    const int m0 = w * 56;                                          // pass2 peer-k base

    // x pointers
    const float* xp0 = x + ((size_t)(b0 + b4)     * Tn) * In + col;
    const float* xp1 = x + ((size_t)(b0 + b4 + 4) * Tn) * In + col;

    // init: own rows of vb[1] (read by pass1 at t=0) zero; stage x(0); mbarrier
    vb[4096 + hg*8 + b4]     = 0.f;
    vb[4096 + hg*8 + b4 + 4] = 0.f;
    xb[col*8 + b4]     = xp0[0];
    xb[col*8 + b4 + 4] = xp1[0];
    if (tid == 0) mbar_init(mbar, 1);
    __syncthreads();
    // all mbarriers initialized before any peer can push
    asm volatile("barrier.cluster.arrive.aligned;" ::: "memory");
    asm volatile("barrier.cluster.wait.aligned;"   ::: "memory");
    if (tid == 0) mbar_expect(mbar, STEP_TX);    // phase 0: hy(0) exchange

    const size_t BTH = (size_t)Bn * Tn * Hn;
    const bool writeFinal = (out_elems >= (long long)(BTH + (size_t)Bn * Hn));

    for (int t = 0; t < Tn; t++) {
        const float* vprev = vb + ((t - 1) & 1) * 4096;
        // prefetch x(t+1): DRAM latency hidden behind the step
        const int tn = (t + 1 < Tn) ? (t + 1) : t;
        const float xn0 = xp0[(size_t)tn * In];
        const float xn1 = xp1[(size_t)tn * In];

        u64 a00=0ull,a01=0ull,a10=0ull,a11=0ull,a20=0ull,a21=0ull,a30=0ull,a31=0ull;

        // ---- pass1: local k (own 64 hy rows + 64 x rows), hides arrival skew
        {
            const float* vr1 = (w < 4) ? (vprev + (c0 + w*16)*8) : (xb + (w - 4)*16*8);
            #pragma unroll 4
            for (int kk = 0; kk < 16; kk++) {
                float2 wv = *(const float2*)(Wr1 + kk*64);
                const ulonglong2* hv = (const ulonglong2*)(vr1 + kk*8);
                ulonglong2 hA = hv[0];
                ulonglong2 hB = hv[1];
                GEMM8(hA, hB, wv);
            }
        }

        if (t > 0) {
            // ---- wait for peers' hy(t-1) pushed into our vbuf
            mbar_wait(mbar, (t - 1) & 1);
            if (t < Tn - 1 && tid == 0) mbar_expect(mbar, STEP_TX);  // next phase
            // ---- pass2: peer k from LOCAL smem (broadcast LDS, conflict-free)
            #pragma unroll 4
            for (int kk = 0; kk < 56; kk++) {
                int m = m0 + kk;
                int h = m + ((m >= c0) ? 64 : 0);
                const ulonglong2* hv = (const ulonglong2*)(vprev + h*8);
                ulonglong2 hA = hv[0];
                ulonglong2 hB = hv[1];
                float2 wv = *(const float2*)(W + h*64 + cg*2);
                GEMM8(hA, hB, wv);
            }
        }

        // ---- stage split-K partials [w][b][col]
        {
            float l0,h0,l1,h1;
            unpack2(a00,l0,h0); unpack2(a01,l1,h1);
            *(float2*)(rw + 0*64) = make_float2(l0,l1);
            *(float2*)(rw + 1*64) = make_float2(h0,h1);
            unpack2(a10,l0,h0); unpack2(a11,l1,h1);
            *(float2*)(rw + 2*64) = make_float2(l0,l1);
            *(float2*)(rw + 3*64) = make_float2(h0,h1);
            unpack2(a20,l0,h0); unpack2(a21,l1,h1);
            *(float2*)(rw + 4*64) = make_float2(l0,l1);
            *(float2*)(rw + 5*64) = make_float2(h0,h1);
            unpack2(a30,l0,h0); unpack2(a31,l1,h1);
            *(float2*)(rw + 6*64) = make_float2(l0,l1);
            *(float2*)(rw + 7*64) = make_float2(h0,h1);
        }
        __syncthreads();

        // ---- reduce + oscillator update
        {
            float s0 = 0.f, s1 = 0.f;
            const float* r0 = rf + b4*64 + col;
            const float* r1 = r0 + 4*64;
            #pragma unroll
            for (int q = 0; q < 8; q++) { s0 += r0[q*512]; s1 += r1[q*512]; }
            float th0 = tanhf(s0 + bia);
            float th1 = tanhf(s1 + bia);
            hz0 += DTc * (th0 - ga*hy0 - ep*hz0);  hy0 += DTc * hz0;
            hz1 += DTc * (th1 - ga*hy1 - ep*hz1);  hy1 += DTc * hz1;

            // own slice into vb[t&1] (local; peers receive it via push below)
            float* vnext = vb + (t & 1)*4096;
            vnext[hg*8 + b4]     = hy0;
            vnext[hg*8 + b4 + 4] = hy1;
            // stage x(t+1)
            xb[col*8 + b4]     = xn0;
            xb[col*8 + b4 + 4] = xn1;
            // outputs (coalesced)
            size_t o0 = ((size_t)(b0 + b4) * Tn + t) * Hn + hg;
            out[o0]                       = hy0;
            out[o0 + (size_t)4 * Tn * Hn] = hy1;
            if (t == Tn - 1 && writeFinal) {
                out[BTH + (size_t)(b0 + b4)     * Hn + hg] = hy0;
                out[BTH + (size_t)(b0 + b4 + 4) * Hn + hg] = hy1;
            }
        }
        __syncthreads();   // own-slice STS drained; rf/xb reads done

        // ---- push own 2KB slice into all 7 peers' vbuf (engine-driven, fire-and-forget)
        if (t < Tn - 1 && tid == 0) {
            asm volatile("fence.proxy.async.shared::cta;" ::: "memory");
            uint32_t src = sbase + VB_OFF + (uint32_t)((t & 1)*16384 + c0*32);
            #pragma unroll
            for (int r = 0; r < 8; r++) {
                if (r == rank) continue;
                dsmem_push(mapa_u32(src, r), src, SLICE_BYTES, mapa_u32(mbar, r));
            }
        }
    }

    // no CTA exits while peers might still touch cluster smem
    asm volatile("barrier.cluster.arrive.aligned;" ::: "memory");
    asm volatile("barrier.cluster.wait.aligned;"   ::: "memory");
}

extern "C" void kernel_launch(void* const* d_in, const int* in_sizes, int n_in,
                              void* d_out, int out_size) {
    const float* x    = (const float*)d_in[0];
    const float* x2h  = (const float*)d_in[1];
    const float* h2h  = (const float*)d_in[2];
    const float* bias = (const float*)d_in[3];
    const float* gam  = (const float*)d_in[4];
    const float* eps  = (const float*)d_in[5];
    float* out = (float*)d_out;
    (void)in_sizes; (void)n_in;

    cudaFuncSetAttribute(ron_kernel, cudaFuncAttributeMaxDynamicSharedMemorySize, SMEM_BYTES);
    ron_kernel<<<128, NT, SMEM_BYTES>>>(x, x2h, h2h, bias, gam, eps, out, (long long)out_size);
}